// round 15
// baseline (speedup 1.0000x reference)
#include <cuda_runtime.h>
#include <math.h>

#define NPIX 16384
#define EDIM 128
#define FDIM 512

typedef unsigned long long u64;
typedef unsigned int u32;

// ---------------- scratch (static, no allocation) ----------------
__device__ float g_xn  [NPIX*EDIM];
__device__ float g_xres[NPIX*EDIM];
__device__ float g_qkv [NPIX*384];
__device__ float g_z0  [NPIX*EDIM];
__device__ float g_t   [4*EDIM*EDIM];
__device__ float g_z2  [NPIX*EDIM];
__device__ float g_z3  [NPIX*EDIM];
__device__ float g_h1  [NPIX*FDIM];

// ---------------- warp reductions ----------------
__device__ __forceinline__ float warp_sum(float v) {
    v += __shfl_xor_sync(0xffffffffu, v, 16);
    v += __shfl_xor_sync(0xffffffffu, v, 8);
    v += __shfl_xor_sync(0xffffffffu, v, 4);
    v += __shfl_xor_sync(0xffffffffu, v, 2);
    v += __shfl_xor_sync(0xffffffffu, v, 1);
    return v;
}

// ---------------- cp.async helpers ----------------
__device__ __forceinline__ u32 s2u(const void* p) {
    u32 a; asm("{ .reg .u64 t; cvta.to.shared.u64 t, %1; cvt.u32.u64 %0, t; }" : "=r"(a) : "l"(p));
    return a;
}
__device__ __forceinline__ void cpa16(u32 dst, const void* src) {
    asm volatile("cp.async.cg.shared.global [%0], [%1], 16;" :: "r"(dst), "l"(src));
}
__device__ __forceinline__ void cpa16z(u32 dst, const void* src, int sz) {
    asm volatile("cp.async.cg.shared.global [%0], [%1], 16, %2;" :: "r"(dst), "l"(src), "r"(sz));
}
#define CPA_COMMIT() asm volatile("cp.async.commit_group;" ::: "memory")
#define CPA_WAIT(n)  asm volatile("cp.async.wait_group " #n ";" ::: "memory")

// ---------------- tf32 mma ----------------
__device__ __forceinline__ void mma16n8k8(float c[4], const u32 a[4], const u32 b[2]) {
    asm volatile(
        "mma.sync.aligned.m16n8k8.row.col.f32.tf32.tf32.f32 "
        "{%0,%1,%2,%3}, {%4,%5,%6,%7}, {%8,%9}, {%0,%1,%2,%3};"
        : "+f"(c[0]), "+f"(c[1]), "+f"(c[2]), "+f"(c[3])
        : "r"(a[0]), "r"(a[1]), "r"(a[2]), "r"(a[3]), "r"(b[0]), "r"(b[1]));
}

// ================= tensor-core GEMM (1xTF32, cp.async double-buffered) ======
// M=128 variant: 512 threads, warp grid 4x4.
#define TC_SMEM 73728

__device__ __forceinline__ void tc_stage_async(const float* __restrict__ src, int ldk, int kc,
                                               u32 dstb, int tid) {
#pragma unroll
    for (int it = 0; it < 2; ++it) {
        int i = tid + it*512;
        int row = i >> 3, c4 = i & 7;
        cpa16(dstb + row*144 + c4*16, src + (size_t)row*ldk + kc + c4*4);
    }
}

__device__ void tc_gemm128(const float* __restrict__ A, const float* __restrict__ B,
                           int K, float* __restrict__ SM) {
    const int tid  = threadIdx.x;
    const int lane = tid & 31;
    const int wid  = tid >> 5;
    const int warpM = wid & 3;
    const int warpN = wid >> 2;
    const int g  = lane >> 2;
    const int t4 = lane & 3;
    const u32 smb = s2u(SM);

    float acc[2][4][4];
#pragma unroll
    for (int mi = 0; mi < 2; ++mi)
#pragma unroll
        for (int ni = 0; ni < 4; ++ni)
#pragma unroll
            for (int r = 0; r < 4; ++r) acc[mi][ni][r] = 0.f;

    const int nch = K >> 5;
    tc_stage_async(A, K, 0, smb, tid);
    tc_stage_async(B, K, 0, smb + 18432, tid);
    CPA_COMMIT();

    for (int ch = 0; ch < nch; ++ch) {
        int cur = ch & 1;
        if (ch + 1 < nch) {
            int nxt = cur ^ 1;
            tc_stage_async(A, K, (ch+1)*32, smb + nxt*36864, tid);
            tc_stage_async(B, K, (ch+1)*32, smb + nxt*36864 + 18432, tid);
            CPA_COMMIT();
            CPA_WAIT(1);
        } else {
            CPA_WAIT(0);
        }
        __syncthreads();
        const float* As = SM + cur*9216;
        const float* Bs = As + 4608;
#pragma unroll
        for (int ks = 0; ks < 4; ++ks) {
            int k = ks*8 + t4;
            u32 ah[2][4];
#pragma unroll
            for (int mi = 0; mi < 2; ++mi) {
                int r0 = warpM*32 + mi*16 + g;
                ah[mi][0] = __float_as_uint(As[r0*36 + k]);
                ah[mi][1] = __float_as_uint(As[(r0+8)*36 + k]);
                ah[mi][2] = __float_as_uint(As[r0*36 + k + 4]);
                ah[mi][3] = __float_as_uint(As[(r0+8)*36 + k + 4]);
            }
#pragma unroll
            for (int ni = 0; ni < 4; ++ni) {
                int n0 = warpN*32 + ni*8 + g;
                u32 bh[2];
                bh[0] = __float_as_uint(Bs[n0*36 + k]);
                bh[1] = __float_as_uint(Bs[n0*36 + k + 4]);
                mma16n8k8(acc[0][ni], ah[0], bh);
                mma16n8k8(acc[1][ni], ah[1], bh);
            }
        }
        __syncthreads();
    }
    float* Ct = SM;
#pragma unroll
    for (int mi = 0; mi < 2; ++mi)
#pragma unroll
        for (int ni = 0; ni < 4; ++ni) {
            int r0 = warpM*32 + mi*16 + g;
            int c0 = warpN*32 + ni*8 + t4*2;
            *(float2*)(Ct + r0*132 + c0)     = make_float2(acc[mi][ni][0], acc[mi][ni][1]);
            *(float2*)(Ct + (r0+8)*132 + c0) = make_float2(acc[mi][ni][2], acc[mi][ni][3]);
        }
    __syncthreads();
}

// ---- M=64 variant: Ct[64x132] = A[64xK]*B[128xK]^T. warp grid 2(M)x8(N). ----
// buffers: As 64x36 (9216B) + Bs 128x36 (18432B) = 27648B each, x2 = 55296B.
#define TC64_SMEM 55296

__device__ void tc_gemm64(const float* __restrict__ A, const float* __restrict__ B,
                          int K, float* __restrict__ SM) {
    const int tid  = threadIdx.x;
    const int lane = tid & 31;
    const int wid  = tid >> 5;
    const int warpM = wid & 1;          // 0..1 (32 rows each)
    const int warpN = wid >> 1;         // 0..7 (16 cols each)
    const int g  = lane >> 2;
    const int t4 = lane & 3;
    const u32 smb = s2u(SM);

    float acc[2][2][4];
#pragma unroll
    for (int mi = 0; mi < 2; ++mi)
#pragma unroll
        for (int ni = 0; ni < 2; ++ni)
#pragma unroll
            for (int r = 0; r < 4; ++r) acc[mi][ni][r] = 0.f;

    const int nch = K >> 5;
    // stage chunk 0
    {
        int row = tid >> 3, c4 = tid & 7;               // A: 512 f4, one per thread
        cpa16(smb + row*144 + c4*16, A + (size_t)row*K + c4*4);
        tc_stage_async(B, K, 0, smb + 9216, tid);        // B: 1024 f4
    }
    CPA_COMMIT();

    for (int ch = 0; ch < nch; ++ch) {
        int cur = ch & 1;
        if (ch + 1 < nch) {
            int nxt = cur ^ 1;
            int kc = (ch+1)*32;
            int row = tid >> 3, c4 = tid & 7;
            cpa16(smb + nxt*27648 + row*144 + c4*16, A + (size_t)row*K + kc + c4*4);
            tc_stage_async(B, K, kc, smb + nxt*27648 + 9216, tid);
            CPA_COMMIT();
            CPA_WAIT(1);
        } else {
            CPA_WAIT(0);
        }
        __syncthreads();
        const float* As = SM + cur*6912;
        const float* Bs = As + 2304;
#pragma unroll
        for (int ks = 0; ks < 4; ++ks) {
            int k = ks*8 + t4;
            u32 ah[2][4];
#pragma unroll
            for (int mi = 0; mi < 2; ++mi) {
                int r0 = warpM*32 + mi*16 + g;
                ah[mi][0] = __float_as_uint(As[r0*36 + k]);
                ah[mi][1] = __float_as_uint(As[(r0+8)*36 + k]);
                ah[mi][2] = __float_as_uint(As[r0*36 + k + 4]);
                ah[mi][3] = __float_as_uint(As[(r0+8)*36 + k + 4]);
            }
#pragma unroll
            for (int ni = 0; ni < 2; ++ni) {
                int n0 = warpN*16 + ni*8 + g;
                u32 bh[2];
                bh[0] = __float_as_uint(Bs[n0*36 + k]);
                bh[1] = __float_as_uint(Bs[n0*36 + k + 4]);
                mma16n8k8(acc[0][ni], ah[0], bh);
                mma16n8k8(acc[1][ni], ah[1], bh);
            }
        }
        __syncthreads();
    }
    float* Ct = SM;
#pragma unroll
    for (int mi = 0; mi < 2; ++mi)
#pragma unroll
        for (int ni = 0; ni < 2; ++ni) {
            int r0 = warpM*32 + mi*16 + g;
            int c0 = warpN*16 + ni*8 + t4*2;
            *(float2*)(Ct + r0*132 + c0)     = make_float2(acc[mi][ni][0], acc[mi][ni][1]);
            *(float2*)(Ct + (r0+8)*132 + c0) = make_float2(acc[mi][ni][2], acc[mi][ni][3]);
        }
    __syncthreads();
}

// ---------------- LN1: x NCHW -> xn, xres NHWC (tiled, pad 136) ----------------
#define LPAD 136
__global__ __launch_bounds__(256) void ln1_kernel(const float* __restrict__ x,
                                                  const float* __restrict__ g,
                                                  const float* __restrict__ b) {
    __shared__ float T[64*LPAD];
    int tid = threadIdx.x;
    int p0  = blockIdx.x * 64;
    int n   = p0 >> 12;
    int yx0 = p0 & 4095;
    const float* base = x + (size_t)n * EDIM * 4096 + yx0;
#pragma unroll 8
    for (int i = tid; i < 64*EDIM; i += 256) {
        int c = i >> 6, p = i & 63;
        T[p*LPAD + c] = base[(size_t)c*4096 + p];
    }
    __syncthreads();
    int wid = tid >> 5, lane = tid & 31;
#pragma unroll
    for (int k = 0; k < 8; ++k) {
        int p = wid*8 + k;
        float4 v = *(const float4*)(T + p*LPAD + lane*4);
        float s  = v.x + v.y + v.z + v.w;
        float ss = v.x*v.x + v.y*v.y + v.z*v.z + v.w*v.w;
        s = warp_sum(s); ss = warp_sum(ss);
        float mean = s * (1.f/128.f);
        float var  = ss * (1.f/128.f) - mean*mean;
        float rstd = rsqrtf(var + 1e-5f);
        int c = lane*4;
        float4 o;
        o.x = (v.x-mean)*rstd*g[c+0] + b[c+0];
        o.y = (v.y-mean)*rstd*g[c+1] + b[c+1];
        o.z = (v.z-mean)*rstd*g[c+2] + b[c+2];
        o.w = (v.w-mean)*rstd*g[c+3] + b[c+3];
        *(float4*)(g_xn   + (size_t)(p0+p)*EDIM + c) = o;
        *(float4*)(g_xres + (size_t)(p0+p)*EDIM + c) = v;
    }
}

// ---------------- QKV (tensor core, M=128) ----------------
__global__ __launch_bounds__(512, 2) void qkv_tc_kernel(
        const float* __restrict__ wq, const float* __restrict__ wk,
        const float* __restrict__ wv, const float* __restrict__ bq,
        const float* __restrict__ bk, const float* __restrict__ bv) {
    extern __shared__ float SM[];
    int by = blockIdx.x, bx = blockIdx.y;
    const float* W    = (bx == 0) ? wq : (bx == 1 ? wk : wv);
    const float* bias = (bx == 0) ? bq : (bx == 1 ? bk : bv);
    tc_gemm128(g_xn + (size_t)by*128*EDIM, W, EDIM, SM);
    int tid = threadIdx.x, row = tid >> 2, q = tid & 3;
    int p = by*128 + row;
    const float* Ct = SM;
#pragma unroll
    for (int j = 0; j < 8; ++j) {
        int col = q*32 + j*4;
        float4 c = *(const float4*)(Ct + row*132 + col);
        c.x += bias[col+0]; c.y += bias[col+1]; c.z += bias[col+2]; c.w += bias[col+3];
        *(float4*)(g_qkv + (size_t)p*384 + bx*128 + col) = c;
    }
}

// ---------------- bilinear t ----------------
__global__ void bil_t_kernel(const float* __restrict__ bil_w,
                             const float* __restrict__ qcoeff) {
    int i = blockIdx.x * blockDim.x + threadIdx.x;
    if (i >= 4*EDIM*EDIM) return;
    int n  = i >> 14;
    int oi = i & 16383;
    const float4* wp = (const float4*)(bil_w + (size_t)oi*64);
    const float4* qp = (const float4*)(qcoeff + (size_t)n*64);
    float s = 0.f;
#pragma unroll
    for (int q = 0; q < 16; ++q) {
        float4 a = wp[q], b = qp[q];
        s += a.x*b.x + a.y*b.y + a.z*b.z + a.w*b.w;
    }
    g_t[(size_t)n*16384 + oi] = s;
}

// ---------------- attention: single 103.5KB halo buffer (2 CTA/SM), cp.async loads ------
#define HALO 14
#define HROW 33
#define ATTN_SMEM (196*HROW*16)   // 103488

__global__ __launch_bounds__(256, 2) void attn_kernel(const float* __restrict__ rel_bias) {
    extern __shared__ float4 S4[];
    __shared__ float s_rb[196];
    int bid = blockIdx.x;
    int n  = bid >> 6;
    int ty = (bid >> 3) & 7;
    int tx = bid & 7;
    int tid  = threadIdx.x;
    int py   = tid >> 5;
    int lane = tid & 31;
    int h    = lane >> 3;
    int px   = lane & 7;
    int pix  = ((n*64) + ty*8 + py)*64 + tx*8 + px;

    float4 q[8];
    const float4* qp = (const float4*)(g_qkv + (size_t)pix*384 + h*32);
#pragma unroll
    for (int d = 0; d < 8; ++d) q[d] = qp[d];

    if (tid < 196) s_rb[tid] = rel_bias[tid];

    const int y0 = ty*8 - 3, x0 = tx*8 - 3;
    const u32 kbase = s2u(S4);

#pragma unroll 1
    for (int i = tid; i < 196*32; i += 256) {
        int r = i >> 5, c = i & 31;
        int hy = r / HALO, hx = r - hy*HALO;
        int gy = y0 + hy, gx = x0 + hx;
        bool inb = ((unsigned)gy < 64u) && ((unsigned)gx < 64u);
        const float* gp = inb ? (g_qkv + (size_t)((n*64 + gy)*64 + gx)*384 + 128 + c*4) : g_qkv;
        cpa16z(kbase + (u32)(r*HROW + c)*16, gp, inb ? 16 : 0);
    }
    CPA_COMMIT();
    CPA_WAIT(0);
    __syncthreads();

    float sc[49];
    for (int iy = 0; iy < 7; ++iy) {
        int rbase = (py + iy)*HALO + px;
#pragma unroll
        for (int ix = 0; ix < 7; ++ix) {
            const float4* kp = S4 + (rbase + ix)*HROW + h*8;
            float s = 0.f;
#pragma unroll
            for (int d = 0; d < 8; ++d) {
                float4 k = kp[d];
                s += q[d].x*k.x + q[d].y*k.y + q[d].z*k.z + q[d].w*k.w;
            }
            sc[iy*7 + ix] = s + s_rb[h*49 + iy*7 + ix];
        }
    }

    float m = sc[0];
#pragma unroll
    for (int i = 1; i < 49; ++i) m = fmaxf(m, sc[i]);
    float sum = 0.f;
#pragma unroll
    for (int i = 0; i < 49; ++i) { sc[i] = __expf(sc[i] - m); sum += sc[i]; }
    float inv = 1.f / sum;
#pragma unroll
    for (int i = 0; i < 49; ++i) sc[i] *= inv;

    __syncthreads();

#pragma unroll 1
    for (int i = tid; i < 196*32; i += 256) {
        int r = i >> 5, c = i & 31;
        int hy = r / HALO, hx = r - hy*HALO;
        int gy = y0 + hy, gx = x0 + hx;
        bool inb = ((unsigned)gy < 64u) && ((unsigned)gx < 64u);
        const float* gp = inb ? (g_qkv + (size_t)((n*64 + gy)*64 + gx)*384 + 256 + c*4) : g_qkv;
        cpa16z(kbase + (u32)(r*HROW + c)*16, gp, inb ? 16 : 0);
    }
    CPA_COMMIT();
    CPA_WAIT(0);
    __syncthreads();

    float4 acc[8];
#pragma unroll
    for (int d = 0; d < 8; ++d) acc[d] = make_float4(0.f, 0.f, 0.f, 0.f);
    for (int iy = 0; iy < 7; ++iy) {
        int rbase = (py + iy)*HALO + px;
#pragma unroll
        for (int ix = 0; ix < 7; ++ix) {
            float w = sc[iy*7 + ix];
            const float4* vp = S4 + (rbase + ix)*HROW + h*8;
#pragma unroll
            for (int d = 0; d < 8; ++d) {
                float4 v = vp[d];
                acc[d].x += w*v.x; acc[d].y += w*v.y;
                acc[d].z += w*v.z; acc[d].w += w*v.w;
            }
        }
    }
    float4* op = (float4*)(g_z0 + (size_t)pix*EDIM + h*32);
#pragma unroll
    for (int d = 0; d < 8; ++d) op[d] = acc[d];
}

// ---------------- z1 + residual + fused LN2 (tensor core, M=64) ----------------
__global__ __launch_bounds__(512, 2) void z1_tc_kernel(const float* __restrict__ bil_b,
                                                       const float* __restrict__ ln2g,
                                                       const float* __restrict__ ln2b) {
    extern __shared__ float SM[];
    int by = blockIdx.x, n = blockIdx.y;     // by 0..63
    tc_gemm64(g_z0 + ((size_t)n*4096 + by*64)*EDIM, g_t + (size_t)n*EDIM*EDIM, EDIM, SM);
    int tid = threadIdx.x, row = tid >> 3, q = tid & 7;
    int p = n*4096 + by*64 + row;
    const float* Ct = SM;
    float4 o[4];
    float s = 0.f, ss = 0.f;
#pragma unroll
    for (int j = 0; j < 4; ++j) {
        int col = q*16 + j*4;
        float4 c  = *(const float4*)(Ct + row*132 + col);
        float4 xr = *(const float4*)(g_xres + (size_t)p*EDIM + col);
        o[j].x = c.x + bil_b[col+0] + xr.x;
        o[j].y = c.y + bil_b[col+1] + xr.y;
        o[j].z = c.z + bil_b[col+2] + xr.z;
        o[j].w = c.w + bil_b[col+3] + xr.w;
        s  += o[j].x + o[j].y + o[j].z + o[j].w;
        ss += o[j].x*o[j].x + o[j].y*o[j].y + o[j].z*o[j].z + o[j].w*o[j].w;
        *(float4*)(g_z2 + (size_t)p*EDIM + col) = o[j];
    }
    s  += __shfl_xor_sync(0xffffffffu, s, 1);
    s  += __shfl_xor_sync(0xffffffffu, s, 2);
    s  += __shfl_xor_sync(0xffffffffu, s, 4);
    ss += __shfl_xor_sync(0xffffffffu, ss, 1);
    ss += __shfl_xor_sync(0xffffffffu, ss, 2);
    ss += __shfl_xor_sync(0xffffffffu, ss, 4);
    float mean = s * (1.f/128.f);
    float var  = ss * (1.f/128.f) - mean*mean;
    float rstd = rsqrtf(var + 1e-5f);
#pragma unroll
    for (int j = 0; j < 4; ++j) {
        int col = q*16 + j*4;
        float4 z;
        z.x = (o[j].x-mean)*rstd*ln2g[col+0] + ln2b[col+0];
        z.y = (o[j].y-mean)*rstd*ln2g[col+1] + ln2b[col+1];
        z.z = (o[j].z-mean)*rstd*ln2g[col+2] + ln2b[col+2];
        z.w = (o[j].w-mean)*rstd*ln2g[col+3] + ln2b[col+3];
        *(float4*)(g_z3 + (size_t)p*EDIM + col) = z;
    }
}

// ---------------- FFN1 (tensor core, M=128): h1 = gelu(z3 @ w1^T + b1) ----------------
__global__ __launch_bounds__(512, 2) void ffn1_tc_kernel(const float* __restrict__ w1,
                                                         const float* __restrict__ b1) {
    extern __shared__ float SM[];
    int by = blockIdx.x, bx = blockIdx.y;
    tc_gemm128(g_z3 + (size_t)by*128*EDIM, w1 + (size_t)bx*128*EDIM, EDIM, SM);
    int tid = threadIdx.x, row = tid >> 2, q = tid & 3;
    int p = by*128 + row;
    const float* Ct = SM;
#pragma unroll
    for (int j = 0; j < 8; ++j) {
        int col = q*32 + j*4;
        float4 c = *(const float4*)(Ct + row*132 + col);
        float4 o;
        float vx = c.x + b1[bx*128 + col+0];
        float vy = c.y + b1[bx*128 + col+1];
        float vz = c.z + b1[bx*128 + col+2];
        float vw = c.w + b1[bx*128 + col+3];
        o.x = 0.5f*vx*(1.0f + erff(vx*0.70710678118654752f));
        o.y = 0.5f*vy*(1.0f + erff(vy*0.70710678118654752f));
        o.z = 0.5f*vz*(1.0f + erff(vz*0.70710678118654752f));
        o.w = 0.5f*vw*(1.0f + erff(vw*0.70710678118654752f));
        *(float4*)(g_h1 + (size_t)p*FDIM + bx*128 + col) = o;
    }
}

// ---------------- FFN2 (tensor core, M=64): out(NCHW) = h1 @ w2^T + b2 + z2 ----------------
__global__ __launch_bounds__(512, 2) void ffn2_tc_kernel(const float* __restrict__ w2,
                                                         const float* __restrict__ b2,
                                                         float* __restrict__ out) {
    extern __shared__ float SM[];
    int by = blockIdx.x;                     // 0..255
    tc_gemm64(g_h1 + (size_t)by*64*FDIM, w2, FDIM, SM);
    int tid = threadIdx.x, row = tid >> 3, q = tid & 7;
    int p = by*64 + row;
    float* Ct = SM;
#pragma unroll
    for (int j = 0; j < 4; ++j) {
        int col = q*16 + j*4;
        float4 c = *(const float4*)(Ct + row*132 + col);
        float4 z = *(const float4*)(g_z2 + (size_t)p*EDIM + col);
        c.x += b2[col+0] + z.x;
        c.y += b2[col+1] + z.y;
        c.z += b2[col+2] + z.z;
        c.w += b2[col+3] + z.w;
        *(float4*)(Ct + row*132 + col) = c;
    }
    __syncthreads();
    int oc = tid >> 2, q2 = tid & 3;         // oc 0..127, q2 0..3 (16 pixels each)
    int n   = by >> 6;
    int yx0 = (by*64) & 4095;
    float* dst = out + ((size_t)n*EDIM + oc)*4096 + yx0 + q2*16;
#pragma unroll
    for (int r4 = 0; r4 < 4; ++r4) {
        int r0 = q2*16 + r4*4;
        float4 v;
        v.x = Ct[(r0+0)*132 + oc];
        v.y = Ct[(r0+1)*132 + oc];
        v.z = Ct[(r0+2)*132 + oc];
        v.w = Ct[(r0+3)*132 + oc];
        *(float4*)(dst + r4*4) = v;
    }
}

// ---------------- launch ----------------
extern "C" void kernel_launch(void* const* d_in, const int* in_sizes, int n_in,
                              void* d_out, int out_size) {
    const float* x        = (const float*)d_in[0];
    const float* qcoeff   = (const float*)d_in[1];
    const float* wq       = (const float*)d_in[2];
    const float* bq       = (const float*)d_in[3];
    const float* wk       = (const float*)d_in[4];
    const float* bk       = (const float*)d_in[5];
    const float* wv       = (const float*)d_in[6];
    const float* bv       = (const float*)d_in[7];
    const float* rel_bias = (const float*)d_in[8];
    const float* ln1_g    = (const float*)d_in[9];
    const float* ln1_b    = (const float*)d_in[10];
    const float* bil_w    = (const float*)d_in[11];
    const float* bil_b    = (const float*)d_in[12];
    const float* ln2_g    = (const float*)d_in[13];
    const float* ln2_b    = (const float*)d_in[14];
    const float* w1       = (const float*)d_in[15];
    const float* b1       = (const float*)d_in[16];
    const float* w2       = (const float*)d_in[17];
    const float* b2       = (const float*)d_in[18];
    float* out = (float*)d_out;

    cudaFuncSetAttribute(attn_kernel, cudaFuncAttributeMaxDynamicSharedMemorySize, ATTN_SMEM);
    cudaFuncSetAttribute(qkv_tc_kernel,  cudaFuncAttributeMaxDynamicSharedMemorySize, TC_SMEM);
    cudaFuncSetAttribute(z1_tc_kernel,   cudaFuncAttributeMaxDynamicSharedMemorySize, TC64_SMEM);
    cudaFuncSetAttribute(ffn1_tc_kernel, cudaFuncAttributeMaxDynamicSharedMemorySize, TC_SMEM);
    cudaFuncSetAttribute(ffn2_tc_kernel, cudaFuncAttributeMaxDynamicSharedMemorySize, TC64_SMEM);

    ln1_kernel    <<<NPIX/64, 256>>>(x, ln1_g, ln1_b);
    qkv_tc_kernel <<<dim3(128, 3), 512, TC_SMEM>>>(wq, wk, wv, bq, bk, bv);
    bil_t_kernel  <<<256, 256>>>(bil_w, qcoeff);
    attn_kernel   <<<256, 256, ATTN_SMEM>>>(rel_bias);
    z1_tc_kernel  <<<dim3(64, 4), 512, TC64_SMEM>>>(bil_b, ln2_g, ln2_b);
    ffn1_tc_kernel<<<dim3(128, 4), 512, TC_SMEM>>>(w1, b1);
    ffn2_tc_kernel<<<256, 512, TC64_SMEM>>>(w2, b2, out);
}

// round 17
// speedup vs baseline: 1.0337x; 1.0337x over previous
#include <cuda_runtime.h>
#include <math.h>

#define NPIX 16384
#define EDIM 128
#define FDIM 512

typedef unsigned long long u64;
typedef unsigned int u32;

// ---------------- scratch (static, no allocation) ----------------
__device__ float g_xn  [NPIX*EDIM];
__device__ float g_xres[NPIX*EDIM];
__device__ float g_qkv [NPIX*384];
__device__ float g_z0  [NPIX*EDIM];
__device__ float g_t   [4*EDIM*EDIM];
__device__ float g_z2  [NPIX*EDIM];
__device__ float g_z3  [NPIX*EDIM];
__device__ float g_h1  [NPIX*FDIM];

// ---------------- warp reductions ----------------
__device__ __forceinline__ float warp_sum(float v) {
    v += __shfl_xor_sync(0xffffffffu, v, 16);
    v += __shfl_xor_sync(0xffffffffu, v, 8);
    v += __shfl_xor_sync(0xffffffffu, v, 4);
    v += __shfl_xor_sync(0xffffffffu, v, 2);
    v += __shfl_xor_sync(0xffffffffu, v, 1);
    return v;
}

// ---------------- cp.async helpers ----------------
__device__ __forceinline__ u32 s2u(const void* p) {
    u32 a; asm("{ .reg .u64 t; cvta.to.shared.u64 t, %1; cvt.u32.u64 %0, t; }" : "=r"(a) : "l"(p));
    return a;
}
__device__ __forceinline__ void cpa16(u32 dst, const void* src) {
    asm volatile("cp.async.cg.shared.global [%0], [%1], 16;" :: "r"(dst), "l"(src));
}
__device__ __forceinline__ void cpa16z(u32 dst, const void* src, int sz) {
    asm volatile("cp.async.cg.shared.global [%0], [%1], 16, %2;" :: "r"(dst), "l"(src), "r"(sz));
}
#define CPA_COMMIT() asm volatile("cp.async.commit_group;" ::: "memory")
#define CPA_WAIT(n)  asm volatile("cp.async.wait_group " #n ";" ::: "memory")

// ---------------- tf32 mma ----------------
__device__ __forceinline__ void mma16n8k8(float c[4], const u32 a[4], const u32 b[2]) {
    asm volatile(
        "mma.sync.aligned.m16n8k8.row.col.f32.tf32.tf32.f32 "
        "{%0,%1,%2,%3}, {%4,%5,%6,%7}, {%8,%9}, {%0,%1,%2,%3};"
        : "+f"(c[0]), "+f"(c[1]), "+f"(c[2]), "+f"(c[3])
        : "r"(a[0]), "r"(a[1]), "r"(a[2]), "r"(a[3]), "r"(b[0]), "r"(b[1]));
}

// ================= tensor-core GEMM (1xTF32, cp.async double-buffered) ======
#define TC_SMEM 73728

__device__ __forceinline__ void tc_stage_async(const float* __restrict__ src, int ldk, int kc,
                                               u32 dstb, int tid) {
#pragma unroll
    for (int it = 0; it < 2; ++it) {
        int i = tid + it*512;
        int row = i >> 3, c4 = i & 7;
        cpa16(dstb + row*144 + c4*16, src + (size_t)row*ldk + kc + c4*4);
    }
}

__device__ void tc_gemm128(const float* __restrict__ A, const float* __restrict__ B,
                           int K, float* __restrict__ SM) {
    const int tid  = threadIdx.x;
    const int lane = tid & 31;
    const int wid  = tid >> 5;
    const int warpM = wid & 3;
    const int warpN = wid >> 2;
    const int g  = lane >> 2;
    const int t4 = lane & 3;
    const u32 smb = s2u(SM);

    float acc[2][4][4];
#pragma unroll
    for (int mi = 0; mi < 2; ++mi)
#pragma unroll
        for (int ni = 0; ni < 4; ++ni)
#pragma unroll
            for (int r = 0; r < 4; ++r) acc[mi][ni][r] = 0.f;

    const int nch = K >> 5;
    tc_stage_async(A, K, 0, smb, tid);
    tc_stage_async(B, K, 0, smb + 18432, tid);
    CPA_COMMIT();

    for (int ch = 0; ch < nch; ++ch) {
        int cur = ch & 1;
        if (ch + 1 < nch) {
            int nxt = cur ^ 1;
            tc_stage_async(A, K, (ch+1)*32, smb + nxt*36864, tid);
            tc_stage_async(B, K, (ch+1)*32, smb + nxt*36864 + 18432, tid);
            CPA_COMMIT();
            CPA_WAIT(1);
        } else {
            CPA_WAIT(0);
        }
        __syncthreads();
        const float* As = SM + cur*9216;
        const float* Bs = As + 4608;
#pragma unroll
        for (int ks = 0; ks < 4; ++ks) {
            int k = ks*8 + t4;
            u32 ah[2][4];
#pragma unroll
            for (int mi = 0; mi < 2; ++mi) {
                int r0 = warpM*32 + mi*16 + g;
                ah[mi][0] = __float_as_uint(As[r0*36 + k]);
                ah[mi][1] = __float_as_uint(As[(r0+8)*36 + k]);
                ah[mi][2] = __float_as_uint(As[r0*36 + k + 4]);
                ah[mi][3] = __float_as_uint(As[(r0+8)*36 + k + 4]);
            }
#pragma unroll
            for (int ni = 0; ni < 4; ++ni) {
                int n0 = warpN*32 + ni*8 + g;
                u32 bh[2];
                bh[0] = __float_as_uint(Bs[n0*36 + k]);
                bh[1] = __float_as_uint(Bs[n0*36 + k + 4]);
                mma16n8k8(acc[0][ni], ah[0], bh);
                mma16n8k8(acc[1][ni], ah[1], bh);
            }
        }
        __syncthreads();
    }
    float* Ct = SM;
#pragma unroll
    for (int mi = 0; mi < 2; ++mi)
#pragma unroll
        for (int ni = 0; ni < 4; ++ni) {
            int r0 = warpM*32 + mi*16 + g;
            int c0 = warpN*32 + ni*8 + t4*2;
            *(float2*)(Ct + r0*132 + c0)     = make_float2(acc[mi][ni][0], acc[mi][ni][1]);
            *(float2*)(Ct + (r0+8)*132 + c0) = make_float2(acc[mi][ni][2], acc[mi][ni][3]);
        }
    __syncthreads();
}

// ---------------- LN1 v3: conflict-free [c][p] transpose (pad 65) ----------------
__global__ __launch_bounds__(256) void ln1_kernel(const float* __restrict__ x,
                                                  const float* __restrict__ g,
                                                  const float* __restrict__ b) {
    __shared__ float T[128*65];
    int tid = threadIdx.x;
    int p0  = blockIdx.x * 64;
    int n   = p0 >> 12;
    int yx0 = p0 & 4095;
    const float* base = x + (size_t)n * EDIM * 4096 + yx0;
    // coalesced f4 global loads; smem stores c*65+p4*4 (<=2-way)
#pragma unroll 4
    for (int i = tid; i < 128*16; i += 256) {
        int c = i >> 4, p4 = i & 15;
        float4 v = *(const float4*)(base + (size_t)c*4096 + p4*4);
        float* d = T + c*65 + p4*4;
        d[0] = v.x; d[1] = v.y; d[2] = v.z; d[3] = v.w;
    }
    __syncthreads();
    int wid = tid >> 5, lane = tid & 31;
#pragma unroll
    for (int k = 0; k < 8; ++k) {
        int p = wid*8 + k;
        float v[4];
        float s = 0.f, ss = 0.f;
#pragma unroll
        for (int j = 0; j < 4; ++j) {
            v[j] = T[(lane + 32*j)*65 + p];   // banks (c+p)%32: conflict-free
            s += v[j]; ss += v[j]*v[j];
        }
        s = warp_sum(s); ss = warp_sum(ss);
        float mean = s * (1.f/128.f);
        float var  = ss * (1.f/128.f) - mean*mean;
        float rstd = rsqrtf(var + 1e-5f);
#pragma unroll
        for (int j = 0; j < 4; ++j) {
            int c = lane + 32*j;
            g_xn  [(size_t)(p0+p)*EDIM + c] = (v[j]-mean)*rstd*g[c] + b[c];
            g_xres[(size_t)(p0+p)*EDIM + c] = v[j];
        }
    }
}

// ---------------- QKV (tensor core, M=128) ----------------
__global__ __launch_bounds__(512, 2) void qkv_tc_kernel(
        const float* __restrict__ wq, const float* __restrict__ wk,
        const float* __restrict__ wv, const float* __restrict__ bq,
        const float* __restrict__ bk, const float* __restrict__ bv) {
    extern __shared__ float SM[];
    int by = blockIdx.x, bx = blockIdx.y;
    const float* W    = (bx == 0) ? wq : (bx == 1 ? wk : wv);
    const float* bias = (bx == 0) ? bq : (bx == 1 ? bk : bv);
    tc_gemm128(g_xn + (size_t)by*128*EDIM, W, EDIM, SM);
    int tid = threadIdx.x, row = tid >> 2, q = tid & 3;
    int p = by*128 + row;
    const float* Ct = SM;
#pragma unroll
    for (int j = 0; j < 8; ++j) {
        int col = q*32 + j*4;
        float4 c = *(const float4*)(Ct + row*132 + col);
        c.x += bias[col+0]; c.y += bias[col+1]; c.z += bias[col+2]; c.w += bias[col+3];
        *(float4*)(g_qkv + (size_t)p*384 + bx*128 + col) = c;
    }
}

// ---------------- bilinear t ----------------
__global__ void bil_t_kernel(const float* __restrict__ bil_w,
                             const float* __restrict__ qcoeff) {
    int i = blockIdx.x * blockDim.x + threadIdx.x;
    if (i >= 4*EDIM*EDIM) return;
    int n  = i >> 14;
    int oi = i & 16383;
    const float4* wp = (const float4*)(bil_w + (size_t)oi*64);
    const float4* qp = (const float4*)(qcoeff + (size_t)n*64);
    float s = 0.f;
#pragma unroll
    for (int q = 0; q < 16; ++q) {
        float4 a = wp[q], b = qp[q];
        s += a.x*b.x + a.y*b.y + a.z*b.z + a.w*b.w;
    }
    g_t[(size_t)n*16384 + oi] = s;
}

// ---------------- attention: single 103.5KB halo buffer (2 CTA/SM), cp.async loads ------
#define HALO 14
#define HROW 33
#define ATTN_SMEM (196*HROW*16)   // 103488

__global__ __launch_bounds__(256, 2) void attn_kernel(const float* __restrict__ rel_bias) {
    extern __shared__ float4 S4[];
    __shared__ float s_rb[196];
    int bid = blockIdx.x;
    int n  = bid >> 6;
    int ty = (bid >> 3) & 7;
    int tx = bid & 7;
    int tid  = threadIdx.x;
    int py   = tid >> 5;
    int lane = tid & 31;
    int h    = lane >> 3;
    int px   = lane & 7;
    int pix  = ((n*64) + ty*8 + py)*64 + tx*8 + px;

    float4 q[8];
    const float4* qp = (const float4*)(g_qkv + (size_t)pix*384 + h*32);
#pragma unroll
    for (int d = 0; d < 8; ++d) q[d] = qp[d];

    if (tid < 196) s_rb[tid] = rel_bias[tid];

    const int y0 = ty*8 - 3, x0 = tx*8 - 3;
    const u32 kbase = s2u(S4);

#pragma unroll 1
    for (int i = tid; i < 196*32; i += 256) {
        int r = i >> 5, c = i & 31;
        int hy = r / HALO, hx = r - hy*HALO;
        int gy = y0 + hy, gx = x0 + hx;
        bool inb = ((unsigned)gy < 64u) && ((unsigned)gx < 64u);
        const float* gp = inb ? (g_qkv + (size_t)((n*64 + gy)*64 + gx)*384 + 128 + c*4) : g_qkv;
        cpa16z(kbase + (u32)(r*HROW + c)*16, gp, inb ? 16 : 0);
    }
    CPA_COMMIT();
    CPA_WAIT(0);
    __syncthreads();

    float sc[49];
    for (int iy = 0; iy < 7; ++iy) {
        int rbase = (py + iy)*HALO + px;
#pragma unroll
        for (int ix = 0; ix < 7; ++ix) {
            const float4* kp = S4 + (rbase + ix)*HROW + h*8;
            float s = 0.f;
#pragma unroll
            for (int d = 0; d < 8; ++d) {
                float4 k = kp[d];
                s += q[d].x*k.x + q[d].y*k.y + q[d].z*k.z + q[d].w*k.w;
            }
            sc[iy*7 + ix] = s + s_rb[h*49 + iy*7 + ix];
        }
    }

    float m = sc[0];
#pragma unroll
    for (int i = 1; i < 49; ++i) m = fmaxf(m, sc[i]);
    float sum = 0.f;
#pragma unroll
    for (int i = 0; i < 49; ++i) { sc[i] = __expf(sc[i] - m); sum += sc[i]; }
    float inv = 1.f / sum;
#pragma unroll
    for (int i = 0; i < 49; ++i) sc[i] *= inv;

    __syncthreads();

#pragma unroll 1
    for (int i = tid; i < 196*32; i += 256) {
        int r = i >> 5, c = i & 31;
        int hy = r / HALO, hx = r - hy*HALO;
        int gy = y0 + hy, gx = x0 + hx;
        bool inb = ((unsigned)gy < 64u) && ((unsigned)gx < 64u);
        const float* gp = inb ? (g_qkv + (size_t)((n*64 + gy)*64 + gx)*384 + 256 + c*4) : g_qkv;
        cpa16z(kbase + (u32)(r*HROW + c)*16, gp, inb ? 16 : 0);
    }
    CPA_COMMIT();
    CPA_WAIT(0);
    __syncthreads();

    float4 acc[8];
#pragma unroll
    for (int d = 0; d < 8; ++d) acc[d] = make_float4(0.f, 0.f, 0.f, 0.f);
    for (int iy = 0; iy < 7; ++iy) {
        int rbase = (py + iy)*HALO + px;
#pragma unroll
        for (int ix = 0; ix < 7; ++ix) {
            float w = sc[iy*7 + ix];
            const float4* vp = S4 + (rbase + ix)*HROW + h*8;
#pragma unroll
            for (int d = 0; d < 8; ++d) {
                float4 v = vp[d];
                acc[d].x += w*v.x; acc[d].y += w*v.y;
                acc[d].z += w*v.z; acc[d].w += w*v.w;
            }
        }
    }
    float4* op = (float4*)(g_z0 + (size_t)pix*EDIM + h*32);
#pragma unroll
    for (int d = 0; d < 8; ++d) op[d] = acc[d];
}

// ---------------- z1 + residual + fused LN2 (tensor core, M=128) ----------------
__global__ __launch_bounds__(512, 2) void z1_tc_kernel(const float* __restrict__ bil_b,
                                                       const float* __restrict__ ln2g,
                                                       const float* __restrict__ ln2b) {
    extern __shared__ float SM[];
    int by = blockIdx.x, n = blockIdx.y;
    tc_gemm128(g_z0 + ((size_t)n*4096 + by*128)*EDIM, g_t + (size_t)n*EDIM*EDIM, EDIM, SM);
    int tid = threadIdx.x, row = tid >> 2, q = tid & 3;
    int p = n*4096 + by*128 + row;
    const float* Ct = SM;
    float4 o[8];
    float s = 0.f, ss = 0.f;
#pragma unroll
    for (int j = 0; j < 8; ++j) {
        int col = q*32 + j*4;
        float4 c  = *(const float4*)(Ct + row*132 + col);
        float4 xr = *(const float4*)(g_xres + (size_t)p*EDIM + col);
        o[j].x = c.x + bil_b[col+0] + xr.x;
        o[j].y = c.y + bil_b[col+1] + xr.y;
        o[j].z = c.z + bil_b[col+2] + xr.z;
        o[j].w = c.w + bil_b[col+3] + xr.w;
        s  += o[j].x + o[j].y + o[j].z + o[j].w;
        ss += o[j].x*o[j].x + o[j].y*o[j].y + o[j].z*o[j].z + o[j].w*o[j].w;
        *(float4*)(g_z2 + (size_t)p*EDIM + col) = o[j];
    }
    s  += __shfl_xor_sync(0xffffffffu, s, 1);
    s  += __shfl_xor_sync(0xffffffffu, s, 2);
    ss += __shfl_xor_sync(0xffffffffu, ss, 1);
    ss += __shfl_xor_sync(0xffffffffu, ss, 2);
    float mean = s * (1.f/128.f);
    float var  = ss * (1.f/128.f) - mean*mean;
    float rstd = rsqrtf(var + 1e-5f);
#pragma unroll
    for (int j = 0; j < 8; ++j) {
        int col = q*32 + j*4;
        float4 z;
        z.x = (o[j].x-mean)*rstd*ln2g[col+0] + ln2b[col+0];
        z.y = (o[j].y-mean)*rstd*ln2g[col+1] + ln2b[col+1];
        z.z = (o[j].z-mean)*rstd*ln2g[col+2] + ln2b[col+2];
        z.w = (o[j].w-mean)*rstd*ln2g[col+3] + ln2b[col+3];
        *(float4*)(g_z3 + (size_t)p*EDIM + col) = z;
    }
}

// ---------------- FFN1 (tensor core, M=128): h1 = gelu(z3 @ w1^T + b1) ----------------
__global__ __launch_bounds__(512, 2) void ffn1_tc_kernel(const float* __restrict__ w1,
                                                         const float* __restrict__ b1) {
    extern __shared__ float SM[];
    int by = blockIdx.x, bx = blockIdx.y;
    tc_gemm128(g_z3 + (size_t)by*128*EDIM, w1 + (size_t)bx*128*EDIM, EDIM, SM);
    int tid = threadIdx.x, row = tid >> 2, q = tid & 3;
    int p = by*128 + row;
    const float* Ct = SM;
#pragma unroll
    for (int j = 0; j < 8; ++j) {
        int col = q*32 + j*4;
        float4 c = *(const float4*)(Ct + row*132 + col);
        float4 o;
        float vx = c.x + b1[bx*128 + col+0];
        float vy = c.y + b1[bx*128 + col+1];
        float vz = c.z + b1[bx*128 + col+2];
        float vw = c.w + b1[bx*128 + col+3];
        o.x = 0.5f*vx*(1.0f + erff(vx*0.70710678118654752f));
        o.y = 0.5f*vy*(1.0f + erff(vy*0.70710678118654752f));
        o.z = 0.5f*vz*(1.0f + erff(vz*0.70710678118654752f));
        o.w = 0.5f*vw*(1.0f + erff(vw*0.70710678118654752f));
        *(float4*)(g_h1 + (size_t)p*FDIM + bx*128 + col) = o;
    }
}

// ---------------- FFN2 (tensor core, M=128): out(NCHW) = h1 @ w2^T + b2 + z2 ----------------
__global__ __launch_bounds__(512, 2) void ffn2_tc_kernel(const float* __restrict__ w2,
                                                         const float* __restrict__ b2,
                                                         float* __restrict__ out) {
    extern __shared__ float SM[];
    int by = blockIdx.x;
    tc_gemm128(g_h1 + (size_t)by*128*FDIM, w2, FDIM, SM);
    int tid = threadIdx.x, row = tid >> 2, q = tid & 3;
    int p = by*128 + row;
    float* Ct = SM;
#pragma unroll
    for (int j = 0; j < 8; ++j) {
        int col = q*32 + j*4;
        float4 c = *(const float4*)(Ct + row*132 + col);
        float4 z = *(const float4*)(g_z2 + (size_t)p*EDIM + col);
        c.x += b2[col+0] + z.x;
        c.y += b2[col+1] + z.y;
        c.z += b2[col+2] + z.z;
        c.w += b2[col+3] + z.w;
        *(float4*)(Ct + row*132 + col) = c;
    }
    __syncthreads();
    int oc = tid >> 2, q2 = tid & 3;
    int n   = by >> 5;
    int yx0 = (by*128) & 4095;
    float* dst = out + ((size_t)n*EDIM + oc)*4096 + yx0 + q2*32;
#pragma unroll
    for (int r4 = 0; r4 < 8; ++r4) {
        int r0 = q2*32 + r4*4;
        float4 v;
        v.x = Ct[(r0+0)*132 + oc];
        v.y = Ct[(r0+1)*132 + oc];
        v.z = Ct[(r0+2)*132 + oc];
        v.w = Ct[(r0+3)*132 + oc];
        *(float4*)(dst + r4*4) = v;
    }
}

// ---------------- launch (single stream, graph-safe) ----------------
extern "C" void kernel_launch(void* const* d_in, const int* in_sizes, int n_in,
                              void* d_out, int out_size) {
    const float* x        = (const float*)d_in[0];
    const float* qcoeff   = (const float*)d_in[1];
    const float* wq       = (const float*)d_in[2];
    const float* bq       = (const float*)d_in[3];
    const float* wk       = (const float*)d_in[4];
    const float* bk       = (const float*)d_in[5];
    const float* wv       = (const float*)d_in[6];
    const float* bv       = (const float*)d_in[7];
    const float* rel_bias = (const float*)d_in[8];
    const float* ln1_g    = (const float*)d_in[9];
    const float* ln1_b    = (const float*)d_in[10];
    const float* bil_w    = (const float*)d_in[11];
    const float* bil_b    = (const float*)d_in[12];
    const float* ln2_g    = (const float*)d_in[13];
    const float* ln2_b    = (const float*)d_in[14];
    const float* w1       = (const float*)d_in[15];
    const float* b1       = (const float*)d_in[16];
    const float* w2       = (const float*)d_in[17];
    const float* b2       = (const float*)d_in[18];
    float* out = (float*)d_out;

    cudaFuncSetAttribute(attn_kernel, cudaFuncAttributeMaxDynamicSharedMemorySize, ATTN_SMEM);
    cudaFuncSetAttribute(qkv_tc_kernel,  cudaFuncAttributeMaxDynamicSharedMemorySize, TC_SMEM);
    cudaFuncSetAttribute(z1_tc_kernel,   cudaFuncAttributeMaxDynamicSharedMemorySize, TC_SMEM);
    cudaFuncSetAttribute(ffn1_tc_kernel, cudaFuncAttributeMaxDynamicSharedMemorySize, TC_SMEM);
    cudaFuncSetAttribute(ffn2_tc_kernel, cudaFuncAttributeMaxDynamicSharedMemorySize, TC_SMEM);

    ln1_kernel    <<<NPIX/64, 256>>>(x, ln1_g, ln1_b);
    qkv_tc_kernel <<<dim3(128, 3), 512, TC_SMEM>>>(wq, wk, wv, bq, bk, bv);
    bil_t_kernel  <<<256, 256>>>(bil_w, qcoeff);
    attn_kernel   <<<256, 256, ATTN_SMEM>>>(rel_bias);
    z1_tc_kernel  <<<dim3(32, 4), 512, TC_SMEM>>>(bil_b, ln2_g, ln2_b);
    ffn1_tc_kernel<<<dim3(128, 4), 512, TC_SMEM>>>(w1, b1);
    ffn2_tc_kernel<<<128, 512, TC_SMEM>>>(w2, b2, out);
}